// round 8
// baseline (speedup 1.0000x reference)
#include <cuda_runtime.h>
#include <cuda_bf16.h>
#include <cstdint>
#include <cstddef>

#define NB 8192
#define ND 128
#define TILE 128
#define NTILE (NB / TILE)       // 64
#define SEGS 10                 // segments per strip-pair
#define NSEG (32 * SEGS)        // grid = 320

#define KPB 272                 // row pitch in bytes (136 halves): conflict-free ldmatrix
#define ATS 34816               // one 128x128 bf16 tile with pitch 272
#define SM_YIS 0
#define SM_YJS 512              // 2 x 512B (double-buffered with B)
#define SM_A   2048             // hi at +0, lo at +ATS (persistent per strip)
#define SM_B   (SM_A + 2 * ATS) // 2 bufs x (hi,lo); buf stride 2*ATS
#define SM_TBL (SM_B + 4 * ATS) // column tables: 2 x 128 x 9 floats
#define SMEM_TOTAL (SM_TBL + 9216)   // 220160 B
#define TPIT 132                // mirror staging pitch (floats)
#define CTS 9                   // column-table stride (floats), 9 invertible mod 32

__device__ __align__(16) float g_S[(size_t)NB * NB];   // 256 MB similarity scratch
__device__ __align__(16) __nv_bfloat16 g_xhi[(size_t)NB * ND];
__device__ __align__(16) __nv_bfloat16 g_xlo[(size_t)NB * ND];
__device__ unsigned g_minpos[NB];
__device__ unsigned g_maxneg[NB];
__device__ int g_y[NB];
__device__ float g_row[NB];
__device__ int   g_valid[NB];
__device__ int   g_is64;

// ---------------- helpers ----------------
__device__ __forceinline__ uint32_t smem_u32(const void* p) {
    uint32_t a;
    asm("{ .reg .u64 t; cvta.to.shared.u64 t, %1; cvt.u32.u64 %0, t; }" : "=r"(a) : "l"(p));
    return a;
}
__device__ __forceinline__ void ldsm4(uint32_t& r0, uint32_t& r1, uint32_t& r2, uint32_t& r3,
                                      uint32_t addr) {
    asm volatile("ldmatrix.sync.aligned.m8n8.x4.shared.b16 {%0,%1,%2,%3}, [%4];"
                 : "=r"(r0), "=r"(r1), "=r"(r2), "=r"(r3) : "r"(addr));
}
__device__ __forceinline__ void mma16816(float* d, const uint32_t* a, const uint32_t* b) {
    asm volatile("mma.sync.aligned.m16n8k16.row.col.f32.bf16.bf16.f32 "
                 "{%0,%1,%2,%3}, {%4,%5,%6,%7}, {%8,%9}, {%0,%1,%2,%3};"
                 : "+f"(d[0]), "+f"(d[1]), "+f"(d[2]), "+f"(d[3])
                 : "r"(a[0]), "r"(a[1]), "r"(a[2]), "r"(a[3]), "r"(b[0]), "r"(b[1]));
}
__device__ __forceinline__ void cpasync16(uint32_t dst, const void* src) {
    asm volatile("cp.async.cg.shared.global [%0], [%1], 16;" :: "r"(dst), "l"(src));
}
#define CP_COMMIT() asm volatile("cp.async.commit_group;" ::: "memory")
#define CP_WAIT0()  asm volatile("cp.async.wait_group 0;" ::: "memory")

// streaming (evict-first) stores: S is written once, read once much later
__device__ __forceinline__ void stg_cs_f2(float* p, float a, float b) {
    asm volatile("st.global.cs.v2.f32 [%0], {%1, %2};" :: "l"(p), "f"(a), "f"(b) : "memory");
}
__device__ __forceinline__ void stg_cs_f4(float* p, float4 v) {
    asm volatile("st.global.cs.v4.f32 [%0], {%1, %2, %3, %4};"
                 :: "l"(p), "f"(v.x), "f"(v.y), "f"(v.z), "f"(v.w) : "memory");
}

__device__ __forceinline__ unsigned fenc(float f) {
    unsigned u = __float_as_uint(f);
    return (u & 0x80000000u) ? ~u : (u | 0x80000000u);
}
__device__ __forceinline__ float fdec(unsigned u) {
    return __uint_as_float((u & 0x80000000u) ? (u ^ 0x80000000u) : ~u);
}

// ---------------- small kernels ----------------
__global__ void detect_kernel(const unsigned* __restrict__ yraw) {
    __shared__ unsigned red[256];
    unsigned acc = 0;
    for (int t = threadIdx.x; t < 2048; t += 256) acc |= yraw[2 * t + 1];
    red[threadIdx.x] = acc;
    __syncthreads();
    for (int s = 128; s; s >>= 1) {
        if (threadIdx.x < s) red[threadIdx.x] |= red[threadIdx.x + s];
        __syncthreads();
    }
    if (threadIdx.x == 0) g_is64 = (red[0] == 0) ? 1 : 0;
}

__global__ void prep_x_kernel(const float* __restrict__ x) {
    int idx = blockIdx.x * 256 + threadIdx.x;
    float v = x[idx];
    __nv_bfloat16 h = __float2bfloat16(v);
    g_xhi[idx] = h;
    g_xlo[idx] = __float2bfloat16(v - __bfloat162float(h));
}

__global__ void init_y_kernel(const void* __restrict__ yraw) {
    int i = blockIdx.x * 256 + threadIdx.x;
    if (i < NB) {
        g_y[i] = g_is64 ? (int)((const long long*)yraw)[i] : ((const int*)yraw)[i];
        g_minpos[i] = fenc(__int_as_float(0x7f800000));
        g_maxneg[i] = fenc(__int_as_float(0xff800000));
    }
}

// ============================================================================
// Pass 1: strip-segmented triangular GEMM. Strip pair p = (strip p: jt=p..63)
// + (strip 63-p: jt=63-p..63), 65 tiles total, cut into SEGS segments.
// A tile resident per strip; B double-buffered per tile; one barrier/tile.
// GEMM hi*hi + hi*lo + lo*hi (fp32 accum); direct + mirror S stores; row
// mining persistent in regs, column mining via shfl-reduced smem tables.
// ============================================================================
__global__ void __launch_bounds__(512, 1) pass1_kernel() {
    extern __shared__ char smem[];
    const uint32_t sb = smem_u32(smem);
    const int tid = threadIdx.x;
    const int w = tid >> 5, l = tid & 31;

    const int p = blockIdx.x / SEGS;
    const int g = blockIdx.x % SEGS;
    const int t0 = (65 * g) / SEGS;
    const int t1 = (65 * (g + 1)) / SEGS;
    const int m = 64 - p;   // boundary between strip p and strip 63-p

    // warp/thread geometry: 4x4 warps of 32x32 tiles
    const int wr = (w & 3) * 32;
    const int wc = (w >> 2) * 32;
    const int gq = l >> 3, lr = l & 7;
    const int q = l >> 2;
    const int e2 = (l & 3) * 2;
    const uint32_t aoff = (uint32_t)((gq & 1) * 8 + lr) * KPB + (uint32_t)(gq >> 1) * 16;
    const uint32_t boff = (uint32_t)((gq >> 1) * 8 + lr) * KPB + (uint32_t)(gq & 1) * 16;
    const uint32_t aHi = sb + SM_A;
    const uint32_t aLo = sb + SM_A + ATS;

    // load-helper decode (512 threads -> 4096 x 16B per 64KB tile)
    const int lpart = tid >> 8;           // 0: hi, 1: lo
    const int lrow = (tid >> 1) & 127;    // row
    const int lhalf = tid & 1;            // 128B half of the 256B row

#pragma unroll 1
    for (int rg = 0; rg < 2; rg++) {
        const int lo = (rg == 0) ? t0 : (t0 > m ? t0 : m);
        const int hi = (rg == 0) ? (t1 < m ? t1 : m) : t1;
        if (lo >= hi) continue;
        const int s = (rg == 0) ? p : 63 - p;
        const int jt0 = (rg == 0) ? p + lo : lo - 1;
        const int cnt = hi - lo;
        const int ib = s * TILE;

        __syncthreads();  // protect A/B/staging from overwrite across subranges

        // prologue: A (hi+lo) + yis + B(jt0) + yjs[0], one commit group
        {
            const __nv_bfloat16* srcp = lpart ? g_xlo : g_xhi;
            const char* sA = (const char*)(srcp + (size_t)(ib + lrow) * ND) + lhalf * 128;
            const uint32_t dA = sb + SM_A + lpart * ATS + lrow * KPB + lhalf * 128;
#pragma unroll
            for (int c = 0; c < 8; c++) cpasync16(dA + c * 16, sA + c * 16);
            const int jB = jt0 * TILE;
            const char* sB = (const char*)(srcp + (size_t)(jB + lrow) * ND) + lhalf * 128;
            const uint32_t dB = sb + SM_B + lpart * ATS + lrow * KPB + lhalf * 128;
#pragma unroll
            for (int c = 0; c < 8; c++) cpasync16(dB + c * 16, sB + c * 16);
            if (tid < 32) cpasync16(sb + SM_YIS + tid * 16, g_y + ib + tid * 4);
            else if (tid < 64) cpasync16(sb + SM_YJS + (tid - 32) * 16, g_y + jB + (tid - 32) * 4);
            CP_COMMIT();
        }

        int rowg[4], yrow[4];
        float mp[4], mn[4];
#pragma unroll
        for (int k4 = 0; k4 < 4; k4++) {
            mp[k4] = __int_as_float(0x7f800000);
            mn[k4] = __int_as_float(0xff800000);
        }

        for (int idx = 0; idx < cnt; idx++) {
            const int buf = idx & 1;
            const int jt = jt0 + idx;
            const int jb = jt * TILE;
            CP_WAIT0();
            __syncthreads();  // B[buf]+yjs[buf] ready; epilogue scribbles of B[buf] done

            if (idx == 0) {
#pragma unroll
                for (int k4 = 0; k4 < 4; k4++) {
                    const int rowi = wr + (k4 >> 1) * 16 + (k4 & 1) * 8 + q;
                    rowg[k4] = ib + rowi;
                    yrow[k4] = ((const int*)(smem + SM_YIS))[rowi];
                }
            }

            // prefetch next B tile
            if (idx + 1 < cnt) {
                const int jn = (jt + 1) * TILE;
                const __nv_bfloat16* srcp = lpart ? g_xlo : g_xhi;
                const char* sB = (const char*)(srcp + (size_t)(jn + lrow) * ND) + lhalf * 128;
                const uint32_t dB = sb + SM_B + (1 - buf) * 2 * ATS + lpart * ATS +
                                    lrow * KPB + lhalf * 128;
#pragma unroll
                for (int c = 0; c < 8; c++) cpasync16(dB + c * 16, sB + c * 16);
                if (tid < 32)
                    cpasync16(sb + SM_YJS + (1 - buf) * 512 + tid * 16, g_y + jn + tid * 4);
                CP_COMMIT();
            }

            float acc[2][4][4];
#pragma unroll
            for (int mi = 0; mi < 2; mi++)
#pragma unroll
                for (int ni = 0; ni < 4; ni++)
#pragma unroll
                    for (int d = 0; d < 4; d++) acc[mi][ni][d] = 0.f;

            const uint32_t bHi = sb + SM_B + buf * 2 * ATS;
            const uint32_t bLo = bHi + ATS;

            // mainloop: no barriers (whole tile resident)
#pragma unroll
            for (int kc = 0; kc < 8; kc++) {
                const uint32_t ka = (uint32_t)kc * 32;
                uint32_t ah[2][4], al[2][4], bh[4][2], bl[4][2];
#pragma unroll
                for (int mi = 0; mi < 2; mi++) {
                    uint32_t o = (uint32_t)(wr + mi * 16) * KPB + aoff + ka;
                    ldsm4(ah[mi][0], ah[mi][1], ah[mi][2], ah[mi][3], aHi + o);
                    ldsm4(al[mi][0], al[mi][1], al[mi][2], al[mi][3], aLo + o);
                }
#pragma unroll
                for (int nq = 0; nq < 2; nq++) {
                    uint32_t o = (uint32_t)(wc + nq * 16) * KPB + boff + ka;
                    ldsm4(bh[nq * 2][0], bh[nq * 2][1], bh[nq * 2 + 1][0], bh[nq * 2 + 1][1], bHi + o);
                    ldsm4(bl[nq * 2][0], bl[nq * 2][1], bl[nq * 2 + 1][0], bl[nq * 2 + 1][1], bLo + o);
                }
#pragma unroll
                for (int mi = 0; mi < 2; mi++)
#pragma unroll
                    for (int ni = 0; ni < 4; ni++) {
                        mma16816(acc[mi][ni], ah[mi], bh[ni]);
                        mma16816(acc[mi][ni], ah[mi], bl[ni]);
                        mma16816(acc[mi][ni], al[mi], bh[ni]);
                    }
            }

            // ---- epilogue: direct store + row mining (into persistent regs) ----
            const int* yjs = (const int*)(smem + SM_YJS + buf * 512);
#pragma unroll
            for (int mi = 0; mi < 2; mi++)
#pragma unroll
                for (int h = 0; h < 2; h++) {
                    const int ridx = mi * 2 + h;
                    float* srow = g_S + (size_t)rowg[ridx] * NB + jb;
#pragma unroll
                    for (int ni = 0; ni < 4; ni++) {
                        const float s0 = acc[mi][ni][h * 2 + 0];
                        const float s1 = acc[mi][ni][h * 2 + 1];
                        const int col = wc + ni * 8 + e2;
                        stg_cs_f2(srow + col, s0, s1);
#pragma unroll
                        for (int e = 0; e < 2; e++) {
                            const float sv = e ? s1 : s0;
                            const int jj = jb + col + e;
                            const int yj = yjs[col + e];
                            if (yj == yrow[ridx]) {
                                if (jj != rowg[ridx]) mp[ridx] = fminf(mp[ridx], sv);
                            } else {
                                mn[ridx] = fmaxf(mn[ridx], sv);
                            }
                        }
                    }
                }

            // ---- off-diagonal: mirror store + column mining ----
            if (jt != s) {
                float pmin[8], pmax[8];
#pragma unroll
                for (int c = 0; c < 8; c++) {
                    pmin[c] = __int_as_float(0x7f800000);
                    pmax[c] = __int_as_float(0xff800000);
                }
#pragma unroll
                for (int mi = 0; mi < 2; mi++)
#pragma unroll
                    for (int h = 0; h < 2; h++) {
                        const int ridx = mi * 2 + h;
#pragma unroll
                        for (int ni = 0; ni < 4; ni++)
#pragma unroll
                            for (int e = 0; e < 2; e++) {
                                const float sv = acc[mi][ni][h * 2 + e];
                                const int c = ni * 2 + e;
                                const int yj = yjs[wc + ni * 8 + e2 + e];
                                if (yj == yrow[ridx]) pmin[c] = fminf(pmin[c], sv);
                                else pmax[c] = fmaxf(pmax[c], sv);
                            }
                    }
                // shfl pre-reduce over q^2, q^4 -> 8 slots per column
#pragma unroll
                for (int c = 0; c < 8; c++) {
                    pmin[c] = fminf(pmin[c], __shfl_xor_sync(0xffffffffu, pmin[c], 8));
                    pmin[c] = fminf(pmin[c], __shfl_xor_sync(0xffffffffu, pmin[c], 16));
                    pmax[c] = fmaxf(pmax[c], __shfl_xor_sync(0xffffffffu, pmax[c], 8));
                    pmax[c] = fmaxf(pmax[c], __shfl_xor_sync(0xffffffffu, pmax[c], 16));
                }
                float* tmin = (float*)(smem + SM_TBL);
                float* tmax = tmin + 128 * CTS;
                if (l < 8) {
                    const int slot = (w & 3) * 2 + (l >> 2);
#pragma unroll
                    for (int ni = 0; ni < 4; ni++)
#pragma unroll
                        for (int e = 0; e < 2; e++) {
                            const int col = wc + ni * 8 + e2 + e;
                            tmin[col * CTS + slot] = pmin[ni * 2 + e];
                            tmax[col * CTS + slot] = pmax[ni * 2 + e];
                        }
                }
                // transpose staging into the (consumed) B[buf] region
                float* stg = (float*)(smem + SM_B + buf * 2 * ATS);
#pragma unroll
                for (int mi = 0; mi < 2; mi++)
#pragma unroll
                    for (int h = 0; h < 2; h++) {
                        const int row = wr + mi * 16 + h * 8 + q;
#pragma unroll
                        for (int ni = 0; ni < 4; ni++) {
                            const int col = wc + ni * 8 + e2;
                            stg[col * TPIT + row] = acc[mi][ni][h * 2 + 0];
                            stg[(col + 1) * TPIT + row] = acc[mi][ni][h * 2 + 1];
                        }
                    }
                __syncthreads();

                if (tid < 128) {
                    const int col = tid;
                    float cmp = __int_as_float(0x7f800000);
                    float cmx = __int_as_float(0xff800000);
#pragma unroll
                    for (int kk = 0; kk < 8; kk++) {
                        cmp = fminf(cmp, tmin[col * CTS + kk]);
                        cmx = fmaxf(cmx, tmax[col * CTS + kk]);
                    }
                    atomicMin(&g_minpos[jb + col], fenc(cmp));
                    atomicMax(&g_maxneg[jb + col], fenc(cmx));
                }
#pragma unroll
                for (int iter = 0; iter < 8; iter++) {
                    const int jr = iter * 16 + w;
                    float4 v = *(const float4*)&stg[jr * TPIT + l * 4];
                    stg_cs_f4(g_S + (size_t)(jb + jr) * NB + ib + l * 4, v);
                }
            }
        }

        // flush persistent row mining
#pragma unroll
        for (int k4 = 0; k4 < 4; k4++) {
            float a = mp[k4], bv = mn[k4];
            a = fminf(a, __shfl_xor_sync(0xffffffffu, a, 1));
            a = fminf(a, __shfl_xor_sync(0xffffffffu, a, 2));
            bv = fmaxf(bv, __shfl_xor_sync(0xffffffffu, bv, 1));
            bv = fmaxf(bv, __shfl_xor_sync(0xffffffffu, bv, 2));
            if ((l & 3) == 0) {
                atomicMin(&g_minpos[rowg[k4]], fenc(a));
                atomicMax(&g_maxneg[rowg[k4]], fenc(bv));
            }
        }
    }
}

// ============================================================================
// Pass 2: per-row mining + exp sums (streams stored S). Deterministic.
// ============================================================================
__global__ void __launch_bounds__(256) pass2_kernel() {
    const int i = blockIdx.x;
    const float minp = fdec(g_minpos[i]);
    const float maxn = fdec(g_maxneg[i]);
    const int yi = g_y[i];

    float psum = 0.f, nsum = 0.f;
    int flags = 0;

    const float4* Srow = (const float4*)(g_S + (size_t)i * NB);
    const int4* y4 = (const int4*)g_y;

    const int c0 = (threadIdx.x + ((blockIdx.x & 7) << 8)) & 2047;
    for (int t = 0; t < 8; t++) {
        const int c = (c0 + t * 256) & 2047;
        float4 s4 = __ldcs(Srow + c);
        int4 yv = y4[c];
        float sv[4] = {s4.x, s4.y, s4.z, s4.w};
        int yy[4] = {yv.x, yv.y, yv.z, yv.w};
        const int j0 = c * 4;
#pragma unroll
        for (int e = 0; e < 4; e++) {
            float s = sv[e];
            int j = j0 + e;
            if (yy[e] != yi) {
                if (s + 0.1f > minp) {
                    flags |= 2;
                    nsum += __expf(50.0f * (s - 1.0f));
                }
            } else if (j != i) {
                if (s - 0.1f < maxn) {
                    flags |= 1;
                    psum += __expf(-2.0f * (s - 1.0f));
                }
            }
        }
    }

    __shared__ float sp[256];
    __shared__ float sn[256];
    __shared__ int fl[256];
    sp[threadIdx.x] = psum;
    sn[threadIdx.x] = nsum;
    fl[threadIdx.x] = flags;
    __syncthreads();
    for (int s = 128; s; s >>= 1) {
        if (threadIdx.x < s) {
            sp[threadIdx.x] += sp[threadIdx.x + s];
            sn[threadIdx.x] += sn[threadIdx.x + s];
            fl[threadIdx.x] |= fl[threadIdx.x + s];
        }
        __syncthreads();
    }
    if (threadIdx.x == 0) {
        int valid = (fl[0] == 3) ? 1 : 0;
        g_row[i] = valid ? (0.5f * log1pf(sp[0]) + 0.02f * log1pf(sn[0])) : 0.f;
        g_valid[i] = valid;
    }
}

__global__ void __launch_bounds__(256) finalize_kernel(float* __restrict__ out) {
    __shared__ float ssum[256];
    __shared__ int scnt[256];
    float s = 0.f;
    int c = 0;
    for (int i = threadIdx.x; i < NB; i += 256) {
        s += g_row[i];
        c += g_valid[i];
    }
    ssum[threadIdx.x] = s;
    scnt[threadIdx.x] = c;
    __syncthreads();
    for (int k = 128; k; k >>= 1) {
        if (threadIdx.x < k) {
            ssum[threadIdx.x] += ssum[threadIdx.x + k];
            scnt[threadIdx.x] += scnt[threadIdx.x + k];
        }
        __syncthreads();
    }
    if (threadIdx.x == 0) {
        int n = scnt[0];
        out[0] = (n > 0) ? (ssum[0] / (float)n) : 0.f;
    }
}

extern "C" void kernel_launch(void* const* d_in, const int* in_sizes, int n_in,
                              void* d_out, int out_size) {
    const float* x = (const float*)d_in[0];
    const void* y = d_in[1];

    cudaFuncSetAttribute(pass1_kernel, cudaFuncAttributeMaxDynamicSharedMemorySize, SMEM_TOTAL);

    detect_kernel<<<1, 256>>>((const unsigned*)y);
    prep_x_kernel<<<NB * ND / 256, 256>>>(x);
    init_y_kernel<<<NB / 256, 256>>>(y);

    pass1_kernel<<<NSEG, 512, SMEM_TOTAL>>>();

    pass2_kernel<<<NB, 256>>>();
    finalize_kernel<<<1, 256>>>((float*)d_out);
}